// round 3
// baseline (speedup 1.0000x reference)
#include <cuda_runtime.h>
#include <math.h>

// Hawkes univariate NLL — single-launch fused version.
// x sorted per row => excitation factorizes into a prefix scan:
//   S[j] = exp(-w x_j) * sum_{i<j} exp(w x_i)  -  (# earlier duplicates of x_j)
// ONE block, 1024 threads, loops over the B=2 rows, block-reduces, and
// thread 0 writes the final scalar loss. Eliminates the second kernel
// launch that ncu showed costing 4.35us of pure overhead.

#define HK_N       8192
#define HK_THREADS 1024
#define HK_VPT     (HK_N / HK_THREADS)   // 8 values per thread
#define HK_T       1.0f
#define HK_REG     0.01f

__global__ __launch_bounds__(HK_THREADS)
void hawkes_fused_kernel(const float* __restrict__ x,
                         const float* __restrict__ mu_p,
                         const float* __restrict__ alpha_p,
                         const float* __restrict__ w_p,
                         float* __restrict__ out, int B) {
    __shared__ float xs[HK_N];
    __shared__ float warp_scan[32];
    __shared__ float red[32];

    const int tid = threadIdx.x;
    const unsigned lane = tid & 31u;
    const unsigned wid  = tid >> 5;

    const float mu    = *mu_p;
    const float alpha = *alpha_p;
    const float w     = *w_p;

    float acc = 0.0f;   // accumulates (neg - pos) over all rows

    for (int b = 0; b < B; b++) {
        const float* __restrict__ xr = x + (size_t)b * HK_N;

        // Load row into shared memory (coalesced, 128B segments).
        #pragma unroll
        for (int i = tid; i < HK_N; i += HK_THREADS) xs[i] = xr[i];
        __syncthreads();

        // ---- Level 1: per-thread sequential inclusive scan of exp(w*x) ----
        const int base = tid * HK_VPT;
        float e[HK_VPT], s[HK_VPT];
        float run = 0.0f;
        #pragma unroll
        for (int k = 0; k < HK_VPT; k++) {
            float xi = xs[base + k];
            e[k] = __expf(w * xi);
            run += e[k];
            s[k] = run;                 // inclusive within thread
        }

        // ---- Level 2: warp inclusive scan of thread totals ----
        float v = run;
        #pragma unroll
        for (int off = 1; off < 32; off <<= 1) {
            float n = __shfl_up_sync(0xffffffffu, v, off);
            if (lane >= (unsigned)off) v += n;
        }
        if (lane == 31u) warp_scan[wid] = v;
        __syncthreads();

        // ---- Level 3: scan of the 32 warp sums (warp 0) ----
        if (wid == 0) {
            float wv = (lane < (HK_THREADS / 32)) ? warp_scan[lane] : 0.0f;
            #pragma unroll
            for (int off = 1; off < 32; off <<= 1) {
                float n = __shfl_up_sync(0xffffffffu, wv, off);
                if (lane >= (unsigned)off) wv += n;
            }
            warp_scan[lane] = wv;       // inclusive scan of warp sums
        }
        __syncthreads();

        // Exclusive prefix of this thread's total across the whole block.
        const float thread_excl = (v - run) + ((wid > 0) ? warp_scan[wid - 1] : 0.0f);

        // ---- Elementwise: excite, pos, neg; accumulate (neg - pos) ----
        #pragma unroll
        for (int k = 0; k < HK_VPT; k++) {
            const int j = base + k;
            const float xj = xs[j];
            // exclusive prefix sum of exp(w*x_i) over i < j
            const float P = thread_excl + s[k] - e[k];

            // duplicate-timestamp correction: earlier equal x contribute
            // exactly 1 each to exp(-w xj)*P but are masked (delta<=0) in
            // the reference.
            float c = 0.0f;
            int p = j - 1;
            while (p >= 0 && xs[p] == xj) { c += 1.0f; --p; }

            float S = __expf(-w * xj) * P - c;
            if (S < 0.0f) S = 0.0f;     // guard fp round-off

            const float excite = alpha * w * S;
            const float pos = __logf(mu + excite);
            const float neg = alpha * (1.0f - __expf(-w * (HK_T - xj)));
            acc += neg - pos;
        }

        // Reuse xs / warp_scan next iteration: make sure everyone is done.
        __syncthreads();
    }

    // ---- Block reduction of acc ----
    #pragma unroll
    for (int off = 16; off > 0; off >>= 1)
        acc += __shfl_down_sync(0xffffffffu, acc, off);
    if (lane == 0u) red[wid] = acc;
    __syncthreads();
    if (wid == 0) {
        float r = (lane < (HK_THREADS / 32)) ? red[lane] : 0.0f;
        #pragma unroll
        for (int off = 16; off > 0; off >>= 1)
            r += __shfl_down_sync(0xffffffffu, r, off);
        if (lane == 0u) {
            out[0] = mu * HK_T + r
                   + HK_REG * (-__logf(mu) - __logf(alpha) - __logf(w));
        }
    }
}

extern "C" void kernel_launch(void* const* d_in, const int* in_sizes, int n_in,
                              void* d_out, int out_size) {
    const float* x     = (const float*)d_in[0];
    const float* mu    = (const float*)d_in[1];
    const float* alpha = (const float*)d_in[2];
    const float* w     = (const float*)d_in[3];
    float* out = (float*)d_out;

    const int total = in_sizes[0];
    const int B = total / HK_N;     // shapes fixed: B=2, N=8192

    hawkes_fused_kernel<<<1, HK_THREADS>>>(x, mu, alpha, w, out, B);
}

// round 4
// speedup vs baseline: 1.6600x; 1.6600x over previous
#include <cuda_runtime.h>
#include <math.h>

// Hawkes univariate NLL — single launch, 8 blocks (2 rows x 4 chunks).
// Sorted x => excitation factorizes:  S[j] = exp(-w x_j) * P[j] - dup(j),
// P[j] = exclusive prefix of exp(w x_i). Cross-chunk prefix handoff via
// device-scope flags (8 co-resident blocks, deadlock-free). Last block
// combines partials in fixed order (deterministic) and writes the scalar.

#define HK_N       8192
#define HK_CHUNKS  4
#define HK_CHUNK   (HK_N / HK_CHUNKS)        // 2048
#define HK_THREADS 1024
#define HK_T       1.0f
#define HK_REG     0.01f
#define HK_MAXBLK  64

__device__ volatile float g_chunk_total[HK_MAXBLK];
__device__ volatile int   g_chunk_ready[HK_MAXBLK];   // zero-init; reset each run
__device__ volatile float g_partial[HK_MAXBLK];
__device__ int            g_done_counter;             // zero-init; reset each run

__device__ __forceinline__ float dup_count(const float* __restrict__ xr,
                                           int j, float xj) {
    // # of earlier elements equal to xj (sorted => contiguous run). Rare path.
    float c = 0.0f;
    int p = j - 1;
    while (p >= 0 && xr[p] == xj) { c += 1.0f; --p; }
    return c;
}

__global__ __launch_bounds__(HK_THREADS)
void hawkes_kernel(const float* __restrict__ x,
                   const float* __restrict__ mu_p,
                   const float* __restrict__ alpha_p,
                   const float* __restrict__ w_p,
                   float* __restrict__ out) {
    __shared__ float warp_scan[32];
    __shared__ float red[32];
    __shared__ float sh_prefix;

    const int blk = blockIdx.x;          // b * HK_CHUNKS + q
    const int b   = blk >> 2;
    const int q   = blk & 3;
    const int tid = threadIdx.x;
    const unsigned lane = tid & 31u;
    const unsigned wid  = tid >> 5;

    const float mu    = *mu_p;
    const float alpha = *alpha_p;
    const float w     = *w_p;

    const float* __restrict__ xr = x + (size_t)b * HK_N;
    const int i0 = q * HK_CHUNK + tid * 2;          // 2 contiguous elems/thread

    const float2 xv = *reinterpret_cast<const float2*>(xr + i0);
    const float e0 = __expf(w * xv.x);
    const float e1 = __expf(w * xv.y);
    const float t  = e0 + e1;

    // ---- warp inclusive scan of thread totals ----
    float v = t;
    #pragma unroll
    for (int off = 1; off < 32; off <<= 1) {
        float n = __shfl_up_sync(0xffffffffu, v, off);
        if (lane >= (unsigned)off) v += n;
    }
    if (lane == 31u) warp_scan[wid] = v;
    __syncthreads();
    if (wid == 0) {
        float wv = warp_scan[lane];
        #pragma unroll
        for (int off = 1; off < 32; off <<= 1) {
            float n = __shfl_up_sync(0xffffffffu, wv, off);
            if (lane >= (unsigned)off) wv += n;
        }
        warp_scan[lane] = wv;
    }
    __syncthreads();

    const float thread_excl  = (v - t) + ((wid > 0) ? warp_scan[wid - 1] : 0.0f);
    const float chunk_total  = warp_scan[31];

    // ---- publish chunk total; gather prefix from earlier chunks of this row ----
    if (tid == 0) {
        g_chunk_total[blk] = chunk_total;
        __threadfence();
        g_chunk_ready[blk] = 1;
        float offp = 0.0f;
        for (int qq = 0; qq < q; qq++) {
            const int id = (b << 2) | qq;
            while (g_chunk_ready[id] == 0) { }
            offp += g_chunk_total[id];      // fixed order: deterministic
        }
        sh_prefix = offp;
    }
    __syncthreads();
    const float prefix = sh_prefix;

    // ---- elementwise ----
    float acc = 0.0f;
    {
        const float xj = xv.x;
        const float P  = prefix + thread_excl;
        float S = __expf(-w * xj) * P - dup_count(xr, i0, xj);
        if (S < 0.0f) S = 0.0f;
        acc += alpha * (1.0f - __expf(-w * (HK_T - xj)))
             - __logf(mu + alpha * w * S);
    }
    {
        const float xj = xv.y;
        const float P  = prefix + thread_excl + e0;
        float c = 0.0f;
        if (xv.x == xj) c = 1.0f + dup_count(xr, i0, xj);  // run extends left
        float S = __expf(-w * xj) * P - c;
        if (S < 0.0f) S = 0.0f;
        acc += alpha * (1.0f - __expf(-w * (HK_T - xj)))
             - __logf(mu + alpha * w * S);
    }

    // ---- block reduction ----
    #pragma unroll
    for (int off = 16; off > 0; off >>= 1)
        acc += __shfl_down_sync(0xffffffffu, acc, off);
    if (lane == 0u) red[wid] = acc;
    __syncthreads();
    if (wid == 0) {
        float r = red[lane];
        #pragma unroll
        for (int off = 16; off > 0; off >>= 1)
            r += __shfl_down_sync(0xffffffffu, r, off);
        if (lane == 0u) {
            g_partial[blk] = r;
            __threadfence();
            const int nblk = gridDim.x;
            const int old = atomicAdd(&g_done_counter, 1);
            if (old == nblk - 1) {
                __threadfence();
                float sum = 0.0f;
                for (int i = 0; i < nblk; i++) sum += g_partial[i];  // fixed order
                out[0] = mu * HK_T + sum
                       + HK_REG * (-__logf(mu) - __logf(alpha) - __logf(w));
                // reset state for the next graph replay
                for (int i = 0; i < nblk; i++) g_chunk_ready[i] = 0;
                g_done_counter = 0;
            }
        }
    }
}

extern "C" void kernel_launch(void* const* d_in, const int* in_sizes, int n_in,
                              void* d_out, int out_size) {
    const float* x     = (const float*)d_in[0];
    const float* mu    = (const float*)d_in[1];
    const float* alpha = (const float*)d_in[2];
    const float* w     = (const float*)d_in[3];
    float* out = (float*)d_out;

    const int total = in_sizes[0];
    const int B = total / HK_N;                 // B=2, N=8192 fixed
    hawkes_kernel<<<B * HK_CHUNKS, HK_THREADS>>>(x, mu, alpha, w, out);
}

// round 5
// speedup vs baseline: 2.0557x; 1.2384x over previous
#include <cuda_runtime.h>
#include <math.h>

// Hawkes univariate NLL — single launch, 2 blocks (one per batch row).
// Sorted x => excitation factorizes:
//   S[j] = exp(-w x_j) * P[j] - dup(j),  P[j] = exclusive prefix of exp(w x_i)
// No cross-block scan dependency (each block owns a full row). Final combine:
// last block (atomic counter) sums the 2 partials in fixed order -> scalar.
// MUFU-reduced: e_j = exp(w x_j) is reused for both exp(-w x_j) (via rcp)
// and exp(-w(T-x_j)) = exp(-wT) * e_j.

#define HK_N       8192
#define HK_THREADS 1024
#define HK_VPT     8
#define HK_T       1.0f
#define HK_REG     0.01f

__device__ volatile float g_partial[8];
__device__ int            g_done_counter;   // zero-init; reset after each run

__device__ __forceinline__ float fast_rcp(float a) {
    float r;
    asm("rcp.approx.f32 %0, %1;" : "=f"(r) : "f"(a));
    return r;
}

__global__ __launch_bounds__(HK_THREADS)
void hawkes_kernel(const float* __restrict__ x,
                   const float* __restrict__ mu_p,
                   const float* __restrict__ alpha_p,
                   const float* __restrict__ w_p,
                   float* __restrict__ out) {
    __shared__ float warp_scan[32];
    __shared__ float lastv[HK_THREADS];   // each thread's last element value
    __shared__ float red[32];

    const int b   = blockIdx.x;
    const int tid = threadIdx.x;
    const unsigned lane = tid & 31u;
    const unsigned wid  = tid >> 5;

    const float mu    = *mu_p;
    const float alpha = *alpha_p;
    const float w     = *w_p;
    const float emwT  = __expf(-w * HK_T);      // exp(-w*T)

    const float* __restrict__ xr = x + (size_t)b * HK_N;
    const int base = tid * HK_VPT;

    // ---- load 8 contiguous values (2x float4, coalesced) ----
    float xv[HK_VPT];
    {
        const float4 a0 = *reinterpret_cast<const float4*>(xr + base);
        const float4 a1 = *reinterpret_cast<const float4*>(xr + base + 4);
        xv[0]=a0.x; xv[1]=a0.y; xv[2]=a0.z; xv[3]=a0.w;
        xv[4]=a1.x; xv[5]=a1.y; xv[6]=a1.z; xv[7]=a1.w;
    }

    // ---- per-thread sequential inclusive scan of e = exp(w*x) ----
    float e[HK_VPT], s[HK_VPT];
    float run = 0.0f;
    #pragma unroll
    for (int k = 0; k < HK_VPT; k++) {
        e[k] = __expf(w * xv[k]);
        run += e[k];
        s[k] = run;
    }

    // ---- warp inclusive scan of thread totals ----
    float v = run;
    #pragma unroll
    for (int off = 1; off < 32; off <<= 1) {
        float n = __shfl_up_sync(0xffffffffu, v, off);
        if (lane >= (unsigned)off) v += n;
    }
    if (lane == 31u) warp_scan[wid] = v;
    lastv[tid] = xv[HK_VPT - 1];
    __syncthreads();

    // ---- scan of 32 warp sums (warp 0) ----
    if (wid == 0) {
        float wv = warp_scan[lane];
        #pragma unroll
        for (int off = 1; off < 32; off <<= 1) {
            float n = __shfl_up_sync(0xffffffffu, wv, off);
            if (lane >= (unsigned)off) wv += n;
        }
        warp_scan[lane] = wv;
    }
    __syncthreads();

    const float thread_excl = (v - run) + ((wid > 0) ? warp_scan[wid - 1] : 0.0f);

    // ---- duplicate-run counts (register chain; global walk only if the
    //      run crosses the thread boundary — astronomically rare) ----
    float c[HK_VPT];
    {
        float c0 = 0.0f;
        if (tid > 0 && xv[0] == lastv[tid - 1]) {
            // general walk: count earlier elements equal to xv[0]
            int p = base - 1;
            while (p >= 0 && xr[p] == xv[0]) { c0 += 1.0f; --p; }
        }
        c[0] = c0;
        #pragma unroll
        for (int k = 1; k < HK_VPT; k++)
            c[k] = (xv[k] == xv[k - 1]) ? c[k - 1] + 1.0f : 0.0f;
    }

    // ---- elementwise: excite, pos, neg ----
    float acc = 0.0f;
    #pragma unroll
    for (int k = 0; k < HK_VPT; k++) {
        const float P = thread_excl + s[k] - e[k];   // exclusive prefix sum
        float S = fast_rcp(e[k]) * P - c[k];          // exp(-w x_j) = 1/e_j
        if (S < 0.0f) S = 0.0f;
        const float pos = __logf(mu + alpha * w * S);
        const float neg = alpha * (1.0f - emwT * e[k]); // exp(-w(T-x)) = e^{-wT} e_j
        acc += neg - pos;
    }

    // ---- block reduction ----
    #pragma unroll
    for (int off = 16; off > 0; off >>= 1)
        acc += __shfl_down_sync(0xffffffffu, acc, off);
    if (lane == 0u) red[wid] = acc;
    __syncthreads();
    if (wid == 0) {
        float r = red[lane];
        #pragma unroll
        for (int off = 16; off > 0; off >>= 1)
            r += __shfl_down_sync(0xffffffffu, r, off);
        if (lane == 0u) {
            g_partial[b] = r;
            __threadfence();
            const int nblk = gridDim.x;
            const int old = atomicAdd(&g_done_counter, 1);
            if (old == nblk - 1) {
                __threadfence();
                float sum = 0.0f;
                for (int i = 0; i < nblk; i++) sum += g_partial[i]; // fixed order
                out[0] = mu * HK_T + sum
                       + HK_REG * (-__logf(mu) - __logf(alpha) - __logf(w));
                g_done_counter = 0;     // reset for next graph replay
            }
        }
    }
}

extern "C" void kernel_launch(void* const* d_in, const int* in_sizes, int n_in,
                              void* d_out, int out_size) {
    const float* x     = (const float*)d_in[0];
    const float* mu    = (const float*)d_in[1];
    const float* alpha = (const float*)d_in[2];
    const float* w     = (const float*)d_in[3];
    float* out = (float*)d_out;

    const int total = in_sizes[0];
    const int B = total / HK_N;                 // B=2, N=8192 fixed
    hawkes_kernel<<<B, HK_THREADS>>>(x, mu, alpha, w, out);
}

// round 6
// speedup vs baseline: 2.3799x; 1.1577x over previous
#include <cuda_runtime.h>
#include <math.h>

// Hawkes univariate NLL — single launch, 2 blocks (one per batch row).
// Sorted x =>  S[j] = exp(-w x_j) * P[j] - dup(j),
//              P[j] = exclusive prefix of exp(w x_i).
// Optimizations this round:
//  * neg term closed form: sum_j alpha(1-e^{-w(T-x_j)}) = alpha(N - e^{-wT} * sum e_j)
//    (sum e_j is the scan row total — free).
//  * common path log identity: log(mu + aw*P/e) = log(mu*e + aw*P) - w*x
//    -> 2 MUFU/elem (ex2+lg2) instead of 3; rcp only on duplicate branch.
//  * single __syncthreads scan (each warp redundantly scans the 32 warp totals).
//  * tail via commutative float atomicAdd (2 blocks -> bitwise deterministic).

#define HK_N       8192
#define HK_THREADS 1024
#define HK_VPT     8
#define HK_T       1.0f
#define HK_REG     0.01f

__device__ float          g_acc;          // zero-init; reset after each run
__device__ int            g_done_counter; // zero-init; reset after each run

__device__ __forceinline__ float fast_rcp(float a) {
    float r;
    asm("rcp.approx.f32 %0, %1;" : "=f"(r) : "f"(a));
    return r;
}

__global__ __launch_bounds__(HK_THREADS)
void hawkes_kernel(const float* __restrict__ x,
                   const float* __restrict__ mu_p,
                   const float* __restrict__ alpha_p,
                   const float* __restrict__ w_p,
                   float* __restrict__ out) {
    __shared__ float warp_scan[32];
    __shared__ float lastv[HK_THREADS];   // each thread's last element value
    __shared__ float red[32];

    const int b   = blockIdx.x;
    const int tid = threadIdx.x;
    const unsigned lane = tid & 31u;
    const unsigned wid  = tid >> 5;

    const float mu    = *mu_p;
    const float alpha = *alpha_p;
    const float w     = *w_p;
    const float aw    = alpha * w;
    const float emwT  = __expf(-w * HK_T);

    const float* __restrict__ xr = x + (size_t)b * HK_N;
    const int base = tid * HK_VPT;

    // ---- load 8 contiguous values (2x float4, coalesced) ----
    float xv[HK_VPT];
    {
        const float4 a0 = *reinterpret_cast<const float4*>(xr + base);
        const float4 a1 = *reinterpret_cast<const float4*>(xr + base + 4);
        xv[0]=a0.x; xv[1]=a0.y; xv[2]=a0.z; xv[3]=a0.w;
        xv[4]=a1.x; xv[5]=a1.y; xv[6]=a1.z; xv[7]=a1.w;
    }

    // ---- per-thread sequential inclusive scan of e = exp(w*x) ----
    float e[HK_VPT], s[HK_VPT];
    float run = 0.0f;
    #pragma unroll
    for (int k = 0; k < HK_VPT; k++) {
        e[k] = __expf(w * xv[k]);
        run += e[k];
        s[k] = run;
    }

    // ---- warp inclusive scan of thread totals ----
    float v = run;
    #pragma unroll
    for (int off = 1; off < 32; off <<= 1) {
        float n = __shfl_up_sync(0xffffffffu, v, off);
        if (lane >= (unsigned)off) v += n;
    }
    if (lane == 31u) warp_scan[wid] = v;
    lastv[tid] = xv[HK_VPT - 1];
    __syncthreads();

    // ---- every warp redundantly scans the 32 warp totals (no 2nd barrier) ----
    float wt = warp_scan[lane];
    #pragma unroll
    for (int off = 1; off < 32; off <<= 1) {
        float n = __shfl_up_sync(0xffffffffu, wt, off);
        if (lane >= (unsigned)off) wt += n;
    }
    const float warp_excl = (wid > 0)
        ? __shfl_sync(0xffffffffu, wt, wid - 1) : 0.0f;
    const float row_total = __shfl_sync(0xffffffffu, wt, 31);

    const float thread_excl = (v - run) + warp_excl;

    // ---- duplicate-run counts (register chain; cross-thread check via smem;
    //      global walk only if a run crosses the thread boundary — rare) ----
    float c[HK_VPT];
    {
        float c0 = 0.0f;
        if (tid > 0 && xv[0] == lastv[tid - 1]) {
            int p = base - 1;
            while (p >= 0 && xr[p] == xv[0]) { c0 += 1.0f; --p; }
        }
        c[0] = c0;
        #pragma unroll
        for (int k = 1; k < HK_VPT; k++)
            c[k] = (xv[k] == xv[k - 1]) ? c[k - 1] + 1.0f : 0.0f;
    }

    // ---- elementwise: acc accumulates -(pos). neg handled in closed form. ----
    float acc = 0.0f;
    #pragma unroll
    for (int k = 0; k < HK_VPT; k++) {
        const float P = thread_excl + s[k] - e[k];   // exclusive prefix sum
        float pos;
        if (c[k] == 0.0f) {
            // log(mu + aw*P/e) = log(mu*e + aw*P) - w*x   (2 MUFU total w/ exp)
            pos = __logf(fmaf(mu, e[k], aw * P)) - w * xv[k];
        } else {
            float S = P * fast_rcp(e[k]) - c[k];
            if (S < 0.0f) S = 0.0f;
            pos = __logf(fmaf(aw, S, mu));
        }
        acc -= pos;
    }

    // closed-form neg for the whole row, added once (deterministic position)
    if (tid == 0)
        acc += alpha * ((float)HK_N - emwT * row_total);

    // ---- block reduction ----
    #pragma unroll
    for (int off = 16; off > 0; off >>= 1)
        acc += __shfl_down_sync(0xffffffffu, acc, off);
    if (lane == 0u) red[wid] = acc;
    __syncthreads();
    if (wid == 0) {
        float r = red[lane];
        #pragma unroll
        for (int off = 16; off > 0; off >>= 1)
            r += __shfl_down_sync(0xffffffffu, r, off);
        if (lane == 0u) {
            atomicAdd(&g_acc, r);          // 2 adds, commutative -> deterministic
            __threadfence();
            const int nblk = gridDim.x;
            const int old = atomicAdd(&g_done_counter, 1);
            if (old == nblk - 1) {
                __threadfence();
                const float sum = *((volatile float*)&g_acc);
                out[0] = mu * HK_T + sum
                       + HK_REG * (-__logf(mu) - __logf(alpha) - __logf(w));
                // reset for next graph replay (kernel-end ordering covers this)
                g_acc = 0.0f;
                g_done_counter = 0;
            }
        }
    }
}

extern "C" void kernel_launch(void* const* d_in, const int* in_sizes, int n_in,
                              void* d_out, int out_size) {
    const float* x     = (const float*)d_in[0];
    const float* mu    = (const float*)d_in[1];
    const float* alpha = (const float*)d_in[2];
    const float* w     = (const float*)d_in[3];
    float* out = (float*)d_out;

    const int total = in_sizes[0];
    const int B = total / HK_N;                 // B=2, N=8192 fixed
    hawkes_kernel<<<B, HK_THREADS>>>(x, mu, alpha, w, out);
}

// round 7
// speedup vs baseline: 2.5441x; 1.0690x over previous
#include <cuda_runtime.h>
#include <math.h>

// Hawkes univariate NLL — single launch, 2 blocks (one per batch row).
// Sorted x =>  S[j] = exp(-w x_j) * P[j] - dup(j),
//              P[j] = exclusive prefix of exp(w x_i).
// This round:
//  * tail: flag handoff (block1 -> block0) instead of 2 global atomics.
//  * epilogue constant (mu*T + reg logs) precomputed right after param load.
//  * depth-3 tree prefix per thread; -w*x folded to one FMA per thread.

#define HK_N       8192
#define HK_THREADS 1024
#define HK_VPT     8
#define HK_T       1.0f
#define HK_REG     0.01f

__device__ volatile float g_r1;     // block 1's partial
__device__ volatile int   g_flag;   // zero-init; reset by block 0 each run

__device__ __forceinline__ float fast_rcp(float a) {
    float r;
    asm("rcp.approx.f32 %0, %1;" : "=f"(r) : "f"(a));
    return r;
}

__global__ __launch_bounds__(HK_THREADS)
void hawkes_kernel(const float* __restrict__ x,
                   const float* __restrict__ mu_p,
                   const float* __restrict__ alpha_p,
                   const float* __restrict__ w_p,
                   float* __restrict__ out) {
    __shared__ float warp_scan[32];
    __shared__ float lastv[HK_THREADS];
    __shared__ float red[32];

    const int b   = blockIdx.x;
    const int tid = threadIdx.x;
    const unsigned lane = tid & 31u;
    const unsigned wid  = tid >> 5;

    const float mu    = *mu_p;
    const float alpha = *alpha_p;
    const float w     = *w_p;
    const float aw    = alpha * w;
    const float emwT  = __expf(-w * HK_T);

    // Epilogue constant — depends only on params; overlaps with everything.
    float base_const = 0.0f;
    if (b == 0 && tid == 0)
        base_const = mu * HK_T
                   + HK_REG * (-__logf(mu) - __logf(alpha) - __logf(w));

    const float* __restrict__ xr = x + (size_t)b * HK_N;
    const int base = tid * HK_VPT;

    // ---- load 8 contiguous values (2x float4, coalesced) ----
    float xv[HK_VPT];
    {
        const float4 a0 = *reinterpret_cast<const float4*>(xr + base);
        const float4 a1 = *reinterpret_cast<const float4*>(xr + base + 4);
        xv[0]=a0.x; xv[1]=a0.y; xv[2]=a0.z; xv[3]=a0.w;
        xv[4]=a1.x; xv[5]=a1.y; xv[6]=a1.z; xv[7]=a1.w;
    }

    // ---- e = exp(w*x); depth-3 tree for total + exclusive prefixes ----
    float e[HK_VPT];
    #pragma unroll
    for (int k = 0; k < HK_VPT; k++) e[k] = __expf(w * xv[k]);

    const float t01 = e[0] + e[1], t23 = e[2] + e[3];
    const float t45 = e[4] + e[5], t67 = e[6] + e[7];
    const float t03 = t01 + t23,   t47 = t45 + t67;
    const float run = t03 + t47;                     // thread total (depth 3)

    float p[HK_VPT];                                 // exclusive prefixes
    p[0] = 0.0f;        p[1] = e[0];
    p[2] = t01;         p[3] = t01 + e[2];
    p[4] = t03;         p[5] = t03 + e[4];
    p[6] = t03 + t45;   p[7] = t03 + t45 + e[6];

    // ---- warp inclusive scan of thread totals ----
    float v = run;
    #pragma unroll
    for (int off = 1; off < 32; off <<= 1) {
        float n = __shfl_up_sync(0xffffffffu, v, off);
        if (lane >= (unsigned)off) v += n;
    }
    if (lane == 31u) warp_scan[wid] = v;
    lastv[tid] = xv[HK_VPT - 1];
    __syncthreads();

    // ---- every warp redundantly scans the 32 warp totals (one barrier) ----
    float wt = warp_scan[lane];
    #pragma unroll
    for (int off = 1; off < 32; off <<= 1) {
        float n = __shfl_up_sync(0xffffffffu, wt, off);
        if (lane >= (unsigned)off) wt += n;
    }
    const float warp_excl = (wid > 0)
        ? __shfl_sync(0xffffffffu, wt, wid - 1) : 0.0f;
    const float row_total = __shfl_sync(0xffffffffu, wt, 31);

    const float thread_excl = (v - run) + warp_excl;

    // ---- duplicate-run counts (register chain; global walk only if a run
    //      crosses a thread boundary — astronomically rare) ----
    float c[HK_VPT];
    {
        float c0 = 0.0f;
        if (tid > 0 && xv[0] == lastv[tid - 1]) {
            int pq = base - 1;
            while (pq >= 0 && xr[pq] == xv[0]) { c0 += 1.0f; --pq; }
        }
        c[0] = c0;
        #pragma unroll
        for (int k = 1; k < HK_VPT; k++)
            c[k] = (xv[k] == xv[k - 1]) ? c[k - 1] + 1.0f : 0.0f;
    }

    // ---- elementwise: acc = -(sum pos); neg in closed form at the end ----
    float acc = 0.0f, sumx = 0.0f;
    #pragma unroll
    for (int k = 0; k < HK_VPT; k++) {
        const float P = thread_excl + p[k];          // exclusive prefix sum
        if (c[k] == 0.0f) {
            // log(mu + aw*P/e) = log(mu*e + aw*P) - w*x
            acc -= __logf(fmaf(mu, e[k], aw * P));
            sumx += xv[k];                           // collect the -w*x terms
        } else {
            float S = P * fast_rcp(e[k]) - c[k];
            if (S < 0.0f) S = 0.0f;
            acc -= __logf(fmaf(aw, S, mu));
        }
    }
    acc = fmaf(w, sumx, acc);                        // one FMA for all -w*x

    // closed-form neg for the whole row, added once
    if (tid == 0)
        acc += alpha * ((float)HK_N - emwT * row_total);

    // ---- block reduction ----
    #pragma unroll
    for (int off = 16; off > 0; off >>= 1)
        acc += __shfl_down_sync(0xffffffffu, acc, off);
    if (lane == 0u) red[wid] = acc;
    __syncthreads();
    if (wid == 0) {
        float r = red[lane];
        #pragma unroll
        for (int off = 16; off > 0; off >>= 1)
            r += __shfl_down_sync(0xffffffffu, r, off);
        if (lane == 0u) {
            if (b == 1) {
                // publish partial to block 0
                g_r1 = r;
                __threadfence();
                g_flag = 1;
            } else {
                // block 0: wait for block 1 (symmetric finish -> short spin)
                while (g_flag == 0) { }
                __threadfence();
                const float r1 = g_r1;
                out[0] = base_const + r + r1;        // fixed order: determin.
                g_flag = 0;                          // reset for next replay
            }
        }
    }
}

extern "C" void kernel_launch(void* const* d_in, const int* in_sizes, int n_in,
                              void* d_out, int out_size) {
    const float* x     = (const float*)d_in[0];
    const float* mu    = (const float*)d_in[1];
    const float* alpha = (const float*)d_in[2];
    const float* w     = (const float*)d_in[3];
    float* out = (float*)d_out;

    const int total = in_sizes[0];
    const int B = total / HK_N;                 // B=2, N=8192 fixed
    hawkes_kernel<<<B, HK_THREADS>>>(x, mu, alpha, w, out);
}